// round 16
// baseline (speedup 1.0000x reference)
#include <cuda_runtime.h>
#include <cstdint>

#define BATCH 256
#define TSTEPS 512
#define IDIM 256
#define HDIM 1024
#define KDIM 1280
#define GROWS 4096             // 4*HDIM packed gate rows
#define NKC (KDIM / 8)         // 160 k-chunks of 8
#define NKCH (HDIM / 8)        // 128 h k-chunks
#define NKCX (IDIM / 8)        // 32 x k-chunks

#define MT 64                  // batch tile per CTA
#define NT 128                 // gate cols per CTA
#define GLD 132                // epilogue smem tile leading dim
#define NTHR 512               // 16 warps: (wm,wn) 32x64 tile x kh K-quarter
#define SMEM_BYTES (4 * MT * GLD * 4)   // four partial gate regions: 135168

// ---------------- persistent device scratch (no allocations allowed) ---------
// B fragment planes: [strip=jt*4+gate][kc(160)][plane(2)][lane(32)][4]
__device__ float g_Wf[(size_t)GROWS * KDIM];
__device__ float g_BiasPack[GROWS];
// h fragments, ping-pong: [(m>>4)][kc(128)][lane][4]
__device__ float g_HXf[2][BATCH * HDIM];
// x fragments for ALL timesteps: [t][(m>>4)][kc(32)][lane][4]
__device__ float g_Xf[(size_t)TSTEPS * BATCH * IDIM];
__device__ float g_C[BATCH * HDIM];         // cell state fp32 (linear)

__device__ __forceinline__ float tf32r(float x) {
    asm("cvt.rna.tf32.f32 %0, %0;" : "+f"(x));
    return x;
}
__device__ __forceinline__ float fsigmoid(float x) {
    return __fdividef(1.f, 1.f + __expf(-x));
}
__device__ __forceinline__ float ftanh(float x) {
    float e = __expf(2.f * fminf(x, 15.f));   // clamp: avoid inf/inf
    return __fdividef(e - 1.f, e + 1.f);
}

// B loads: streaming in L1 (evict_first), normal in L2 (Wf stays L2-resident)
__device__ __forceinline__ float4 ldg_b(const float4* p) {
    float4 v;
    asm("ld.global.nc.L1::evict_first.v4.f32 {%0,%1,%2,%3}, [%4];"
        : "=f"(v.x), "=f"(v.y), "=f"(v.z), "=f"(v.w) : "l"(p));
    return v;
}

// h-fragment index for element (m, k), k < HDIM
__device__ __forceinline__ int hfrag_idx(int m, int k) {
    int rr = m & 15, kc = k >> 3, kk = k & 7;
    int lane = (rr & 7) * 4 + (kk & 3);
    int r = (rr >> 3) + 2 * (kk >> 2);
    return (((m >> 4) * NKCH + kc) * 32 + lane) * 4 + r;
}

// m16n8k8 tf32 mma
__device__ __forceinline__ void mma8(float* c, float4 a, float bx, float by) {
    asm volatile(
        "mma.sync.aligned.m16n8k8.row.col.f32.tf32.tf32.f32 "
        "{%0,%1,%2,%3}, {%4,%5,%6,%7}, {%8,%9}, {%0,%1,%2,%3};"
        : "+f"(c[0]), "+f"(c[1]), "+f"(c[2]), "+f"(c[3])
        : "r"(__float_as_uint(a.x)), "r"(__float_as_uint(a.y)),
          "r"(__float_as_uint(a.z)), "r"(__float_as_uint(a.w)),
          "r"(__float_as_uint(bx)), "r"(__float_as_uint(by)));
}

#define MMA_BODY()                      \
    mma8(acc[0][0], a0, b0.x, b0.y);    \
    mma8(acc[1][0], a1, b0.x, b0.y);    \
    mma8(acc[0][1], a0, b0.z, b0.w);    \
    mma8(acc[1][1], a1, b0.z, b0.w);    \
    mma8(acc[0][2], a0, b1.x, b1.y);    \
    mma8(acc[1][2], a1, b1.x, b1.y);    \
    mma8(acc[0][3], a0, b1.z, b1.w);    \
    mma8(acc[1][3], a1, b1.z, b1.w);    \
    mma8(acc[0][4], a0, b2.x, b2.y);    \
    mma8(acc[1][4], a1, b2.x, b2.y);    \
    mma8(acc[0][5], a0, b2.z, b2.w);    \
    mma8(acc[1][5], a1, b2.z, b2.w);    \
    mma8(acc[0][6], a0, b3.x, b3.y);    \
    mma8(acc[1][6], a1, b3.x, b3.y);    \
    mma8(acc[0][7], a0, b3.z, b3.w);    \
    mma8(acc[1][7], a1, b3.z, b3.w)

// ------------------------------ setup kernels -------------------------------
__global__ void k_convert(const float* __restrict__ w_ih, const float* __restrict__ w_hh,
                          const float* __restrict__ b_ih, const float* __restrict__ b_hh) {
    size_t total = (size_t)GROWS * KDIM;
    for (size_t idx = blockIdx.x * (size_t)blockDim.x + threadIdx.x; idx < total;
         idx += (size_t)gridDim.x * blockDim.x) {
        int j     = (int)(idx & 3);
        int e     = j & 1;
        int nbl   = j >> 1;
        int lane  = (int)((idx >> 2) & 31);
        int plane = (int)((idx >> 7) & 1);
        int rest  = (int)(idx >> 8);
        int kc = rest % NKC;
        int strip = rest / NKC;
        int gate = strip & 3, jt = strip >> 2;
        int nb = plane * 2 + nbl;
        int hr = nb * 8 + (lane >> 2);
        int g_row = gate * HDIM + jt * 32 + hr;
        int k = kc * 8 + (lane & 3) + e * 4;
        float v = (k < HDIM) ? w_hh[(size_t)g_row * HDIM + k]
                             : w_ih[(size_t)g_row * IDIM + (k - HDIM)];
        g_Wf[idx] = tf32r(v);
    }
    for (int p = blockIdx.x * blockDim.x + threadIdx.x; p < GROWS;
         p += gridDim.x * blockDim.x) {
        int jt = p >> 7, gate = (p >> 5) & 3, hr = p & 31;
        int g_row = gate * HDIM + jt * 32 + hr;
        g_BiasPack[p] = b_ih[g_row] + b_hh[g_row];
    }
}

__global__ void k_init() {
    int idx = blockIdx.x * blockDim.x + threadIdx.x;
    if (idx >= BATCH * HDIM) return;
    g_HXf[0][idx] = 0.f;
    g_C[idx] = 0.f;
}

// stage ALL x_t into fragment order (tf32-rounded), coalesced dest
__global__ void k_xstage(const float* __restrict__ ts) {
    size_t total = (size_t)TSTEPS * BATCH * IDIM;
    for (size_t idx = blockIdx.x * (size_t)blockDim.x + threadIdx.x; idx < total;
         idx += (size_t)gridDim.x * blockDim.x) {
        int r     = (int)(idx & 3);
        int lane  = (int)((idx >> 2) & 31);
        int kc    = (int)((idx >> 7) & 31);
        int strip = (int)((idx >> 12) & 15);
        int t     = (int)(idx >> 16);
        int m  = strip * 16 + (lane >> 2) + 8 * (r & 1);
        int kl = kc * 8 + (lane & 3) + 4 * (r >> 1);
        g_Xf[idx] = tf32r(ts[((size_t)m * TSTEPS + t) * IDIM + kl]);
    }
}

// ------------------------------- LSTM timestep -------------------------------
// gates = [h|x] @ Wpack^T via mma.m16n8k8, warp tile 32x64, symmetric 4-way
// K-split; B loads L1-streaming; single-pass 4-region reduction; fused epilogue.
__global__ __launch_bounds__(NTHR, 1) void k_step(int t) {
    extern __shared__ float Gsm[];    // [4][MT][GLD] partial gate regions

    const float* __restrict__ HXr = g_HXf[t & 1];
    float* __restrict__ HXw = g_HXf[(t + 1) & 1];
    const float* __restrict__ Xf = g_Xf + (size_t)t * (BATCH * IDIM);

    const int jt = blockIdx.x;        // 0..31
    const int mt = blockIdx.y;        // 0..3
    const int m0 = mt * MT;
    const int p0 = jt * NT;

    const int tid = threadIdx.x;
    const int wid = tid >> 5, lid = tid & 31;
    const int kh = wid >> 2;          // 0..3 -> K quarter
    const int wm = wid & 1;           // 32-row half
    const int wn = (wid >> 1) & 1;    // 64-col half

    float acc[2][8][4] = {};

    // ---- h part: 32 kc from ping-pong h fragments ----
    {
        const float4* __restrict__ A0 =
            (const float4*)HXr + ((size_t)(mt * 4 + wm * 2) * NKCH + kh * 32) * 32 + lid;
        const float4* __restrict__ A1 = A0 + (size_t)NKCH * 32;
        const float4* __restrict__ B0 =
            (const float4*)g_Wf + ((size_t)(jt * 4 + wn * 2) * NKC + kh * 32) * 64 + lid;
        const float4* __restrict__ B1 = B0 + (size_t)NKC * 64;
#pragma unroll 8
        for (int i = 0; i < 32; ++i) {
            float4 a0 = __ldg(A0 + (size_t)i * 32);
            float4 a1 = __ldg(A1 + (size_t)i * 32);
            float4 b0 = ldg_b(B0 + (size_t)i * 64);
            float4 b1 = ldg_b(B0 + (size_t)i * 64 + 32);
            float4 b2 = ldg_b(B1 + (size_t)i * 64);
            float4 b3 = ldg_b(B1 + (size_t)i * 64 + 32);
            MMA_BODY();
        }
    }
    // ---- x part: 8 kc from pre-staged x fragments ----
    {
        const float4* __restrict__ A0 =
            (const float4*)Xf + ((size_t)(mt * 4 + wm * 2) * NKCX + kh * 8) * 32 + lid;
        const float4* __restrict__ A1 = A0 + (size_t)NKCX * 32;
        const float4* __restrict__ B0 =
            (const float4*)g_Wf + ((size_t)(jt * 4 + wn * 2) * NKC + NKCH + kh * 8) * 64 + lid;
        const float4* __restrict__ B1 = B0 + (size_t)NKC * 64;
#pragma unroll
        for (int i = 0; i < 8; ++i) {
            float4 a0 = __ldg(A0 + (size_t)i * 32);
            float4 a1 = __ldg(A1 + (size_t)i * 32);
            float4 b0 = ldg_b(B0 + (size_t)i * 64);
            float4 b1 = ldg_b(B0 + (size_t)i * 64 + 32);
            float4 b2 = ldg_b(B1 + (size_t)i * 64);
            float4 b3 = ldg_b(B1 + (size_t)i * 64 + 32);
            MMA_BODY();
        }
    }

    // single-pass: each kh quarter stores to its own region; one barrier
    {
        float* Gr = Gsm + kh * (MT * GLD);
        const int row = wm * 32 + (lid >> 2);
        const int col = wn * 64 + 2 * (lid & 3);
#pragma unroll
        for (int i = 0; i < 2; ++i)
#pragma unroll
            for (int nb = 0; nb < 8; ++nb) {
                *(float2*)(Gr + (row + i * 16) * GLD + col + nb * 8) =
                    make_float2(acc[i][nb][0], acc[i][nb][1]);
                *(float2*)(Gr + (row + i * 16 + 8) * GLD + col + nb * 8) =
                    make_float2(acc[i][nb][2], acc[i][nb][3]);
            }
    }
    __syncthreads();

    // fused LSTM cell update: 64 batch rows x 32 hidden units (sum 4 regions)
    const float* Ga = Gsm;
    const float* Gb = Gsm + MT * GLD;
    const float* Gc = Gsm + 2 * MT * GLD;
    const float* Gd = Gsm + 3 * MT * GLD;
    for (int q = tid; q < MT * 32; q += NTHR) {
        int ml = q >> 5, hh = q & 31;
        int base = ml * GLD + hh;
        float il = (Ga[base]      + Gb[base])      + (Gc[base]      + Gd[base])      + g_BiasPack[p0 + hh];
        float fl = (Ga[base + 32] + Gb[base + 32]) + (Gc[base + 32] + Gd[base + 32]) + g_BiasPack[p0 + 32 + hh];
        float gl = (Ga[base + 64] + Gb[base + 64]) + (Gc[base + 64] + Gd[base + 64]) + g_BiasPack[p0 + 64 + hh];
        float ol = (Ga[base + 96] + Gb[base + 96]) + (Gc[base + 96] + Gd[base + 96]) + g_BiasPack[p0 + 96 + hh];
        float ig = fsigmoid(il);
        float fg = fsigmoid(fl);
        float gt = ftanh(gl);
        float og = fsigmoid(ol);
        int m = m0 + ml;
        int hcol = jt * 32 + hh;
        float c = fg * g_C[m * HDIM + hcol] + ig * gt;
        g_C[m * HDIM + hcol] = c;
        HXw[hfrag_idx(m, hcol)] = tf32r(og * ftanh(c));
    }
}

// out[m] = c[m,:] . fc_w + fc_b
__global__ void k_fc(const float* __restrict__ fc_w, const float* __restrict__ fc_b,
                     float* __restrict__ out) {
    int m = blockIdx.x;
    float s = 0.f;
    for (int k = threadIdx.x; k < HDIM; k += blockDim.x)
        s += g_C[m * HDIM + k] * fc_w[k];
#pragma unroll
    for (int o = 16; o; o >>= 1) s += __shfl_xor_sync(0xffffffffu, s, o);
    __shared__ float red[32];
    if ((threadIdx.x & 31) == 0) red[threadIdx.x >> 5] = s;
    __syncthreads();
    if (threadIdx.x < 32) {
        float v = (threadIdx.x < (int)(blockDim.x >> 5)) ? red[threadIdx.x] : 0.f;
#pragma unroll
        for (int o = 16; o; o >>= 1) v += __shfl_xor_sync(0xffffffffu, v, o);
        if (threadIdx.x == 0) out[m] = v + fc_b[0];
    }
}

extern "C" void kernel_launch(void* const* d_in, const int* in_sizes, int n_in,
                              void* d_out, int out_size) {
    (void)in_sizes; (void)n_in; (void)out_size;
    const float* ts   = (const float*)d_in[0];
    const float* w_ih = (const float*)d_in[1];
    const float* w_hh = (const float*)d_in[2];
    const float* b_ih = (const float*)d_in[3];
    const float* b_hh = (const float*)d_in[4];
    const float* fc_w = (const float*)d_in[5];
    const float* fc_b = (const float*)d_in[6];
    float* out = (float*)d_out;

    cudaFuncSetAttribute(k_step, cudaFuncAttributeMaxDynamicSharedMemorySize, SMEM_BYTES);

    k_convert<<<512, 256>>>(w_ih, w_hh, b_ih, b_hh);
    k_init<<<(BATCH * HDIM + 255) / 256, 256>>>();
    k_xstage<<<2048, 256>>>(ts);

    dim3 grid(32, 4);
    for (int t = 0; t < TSTEPS; ++t)
        k_step<<<grid, NTHR, SMEM_BYTES>>>(t);

    k_fc<<<BATCH, 256>>>(fc_w, fc_b, out);
}

// round 17
// speedup vs baseline: 1.2793x; 1.2793x over previous
#include <cuda_runtime.h>
#include <cstdint>

#define BATCH 256
#define TSTEPS 512
#define IDIM 256
#define HDIM 1024
#define KDIM 1280
#define GROWS 4096             // 4*HDIM packed gate rows
#define NKC (KDIM / 8)         // 160 k-chunks of 8
#define NKCH (HDIM / 8)        // 128 h k-chunks
#define NKCX (IDIM / 8)        // 32 x k-chunks

#define MT 64                  // batch tile per CTA
#define NT 128                 // gate cols per CTA
#define GLD 132                // epilogue smem tile leading dim
#define NTHR 512               // 16 warps: (wm,wn) 32x64 tile x kh K-quarter
#define SMEM_BYTES (4 * MT * GLD * 4)   // four partial gate regions: 135168

// ---------------- persistent device scratch (no allocations allowed) ---------
// B fragment planes: [strip=jt*4+gate][kc(160)][plane(2)][lane(32)][4]
__device__ float g_Wf[(size_t)GROWS * KDIM];
__device__ float g_BiasPack[GROWS];
// h fragments, ping-pong: [(m>>4)][kc(128)][lane][4]
__device__ float g_HXf[2][BATCH * HDIM];
// x fragments for ALL timesteps: [t][(m>>4)][kc(32)][lane][4]
__device__ float g_Xf[(size_t)TSTEPS * BATCH * IDIM];
// cell state, SAME fragment layout as h (coalesced epilogue I/O)
__device__ float g_Cf[BATCH * HDIM];

__device__ __forceinline__ float tf32r(float x) {
    asm("cvt.rna.tf32.f32 %0, %0;" : "+f"(x));
    return x;
}
__device__ __forceinline__ float fsigmoid(float x) {
    return __fdividef(1.f, 1.f + __expf(-x));
}
__device__ __forceinline__ float ftanh(float x) {
    float e = __expf(2.f * fminf(x, 15.f));   // clamp: avoid inf/inf
    return __fdividef(e - 1.f, e + 1.f);
}

// h-fragment index for element (m, k), k < HDIM
__device__ __forceinline__ int hfrag_idx(int m, int k) {
    int rr = m & 15, kc = k >> 3, kk = k & 7;
    int lane = (rr & 7) * 4 + (kk & 3);
    int r = (rr >> 3) + 2 * (kk >> 2);
    return (((m >> 4) * NKCH + kc) * 32 + lane) * 4 + r;
}

// m16n8k8 tf32 mma
__device__ __forceinline__ void mma8(float* c, float4 a, float bx, float by) {
    asm volatile(
        "mma.sync.aligned.m16n8k8.row.col.f32.tf32.tf32.f32 "
        "{%0,%1,%2,%3}, {%4,%5,%6,%7}, {%8,%9}, {%0,%1,%2,%3};"
        : "+f"(c[0]), "+f"(c[1]), "+f"(c[2]), "+f"(c[3])
        : "r"(__float_as_uint(a.x)), "r"(__float_as_uint(a.y)),
          "r"(__float_as_uint(a.z)), "r"(__float_as_uint(a.w)),
          "r"(__float_as_uint(bx)), "r"(__float_as_uint(by)));
}

#define MMA_BODY()                      \
    mma8(acc[0][0], a0, b0.x, b0.y);    \
    mma8(acc[1][0], a1, b0.x, b0.y);    \
    mma8(acc[0][1], a0, b0.z, b0.w);    \
    mma8(acc[1][1], a1, b0.z, b0.w);    \
    mma8(acc[0][2], a0, b1.x, b1.y);    \
    mma8(acc[1][2], a1, b1.x, b1.y);    \
    mma8(acc[0][3], a0, b1.z, b1.w);    \
    mma8(acc[1][3], a1, b1.z, b1.w);    \
    mma8(acc[0][4], a0, b2.x, b2.y);    \
    mma8(acc[1][4], a1, b2.x, b2.y);    \
    mma8(acc[0][5], a0, b2.z, b2.w);    \
    mma8(acc[1][5], a1, b2.z, b2.w);    \
    mma8(acc[0][6], a0, b3.x, b3.y);    \
    mma8(acc[1][6], a1, b3.x, b3.y);    \
    mma8(acc[0][7], a0, b3.z, b3.w);    \
    mma8(acc[1][7], a1, b3.z, b3.w)

// ------------------------------ setup kernels -------------------------------
__global__ void k_convert(const float* __restrict__ w_ih, const float* __restrict__ w_hh,
                          const float* __restrict__ b_ih, const float* __restrict__ b_hh) {
    size_t total = (size_t)GROWS * KDIM;
    for (size_t idx = blockIdx.x * (size_t)blockDim.x + threadIdx.x; idx < total;
         idx += (size_t)gridDim.x * blockDim.x) {
        int j     = (int)(idx & 3);
        int e     = j & 1;
        int nbl   = j >> 1;
        int lane  = (int)((idx >> 2) & 31);
        int plane = (int)((idx >> 7) & 1);
        int rest  = (int)(idx >> 8);
        int kc = rest % NKC;
        int strip = rest / NKC;
        int gate = strip & 3, jt = strip >> 2;
        int nb = plane * 2 + nbl;
        int hr = nb * 8 + (lane >> 2);
        int g_row = gate * HDIM + jt * 32 + hr;
        int k = kc * 8 + (lane & 3) + e * 4;
        float v = (k < HDIM) ? w_hh[(size_t)g_row * HDIM + k]
                             : w_ih[(size_t)g_row * IDIM + (k - HDIM)];
        g_Wf[idx] = tf32r(v);
    }
    for (int p = blockIdx.x * blockDim.x + threadIdx.x; p < GROWS;
         p += gridDim.x * blockDim.x) {
        int jt = p >> 7, gate = (p >> 5) & 3, hr = p & 31;
        int g_row = gate * HDIM + jt * 32 + hr;
        g_BiasPack[p] = b_ih[g_row] + b_hh[g_row];
    }
}

__global__ void k_init() {
    int idx = blockIdx.x * blockDim.x + threadIdx.x;
    if (idx >= BATCH * HDIM) return;
    g_HXf[0][idx] = 0.f;
    g_Cf[idx] = 0.f;
}

// stage ALL x_t into fragment order (tf32-rounded), coalesced dest
__global__ void k_xstage(const float* __restrict__ ts) {
    size_t total = (size_t)TSTEPS * BATCH * IDIM;
    for (size_t idx = blockIdx.x * (size_t)blockDim.x + threadIdx.x; idx < total;
         idx += (size_t)gridDim.x * blockDim.x) {
        int r     = (int)(idx & 3);
        int lane  = (int)((idx >> 2) & 31);
        int kc    = (int)((idx >> 7) & 31);
        int strip = (int)((idx >> 12) & 15);
        int t     = (int)(idx >> 16);
        int m  = strip * 16 + (lane >> 2) + 8 * (r & 1);
        int kl = kc * 8 + (lane & 3) + 4 * (r >> 1);
        g_Xf[idx] = tf32r(ts[((size_t)m * TSTEPS + t) * IDIM + kl]);
    }
}

// ------------------------------- LSTM timestep -------------------------------
// gates = [h|x] @ Wpack^T via mma.m16n8k8, warp tile 32x64, symmetric 4-way
// K-split; single-pass 4-region reduction; fragment-ordered coalesced epilogue.
__global__ __launch_bounds__(NTHR, 1) void k_step(int t) {
    extern __shared__ float Gsm[];    // [4][MT][GLD] partial gate regions

    const float* __restrict__ HXr = g_HXf[t & 1];
    float* __restrict__ HXw = g_HXf[(t + 1) & 1];
    const float* __restrict__ Xf = g_Xf + (size_t)t * (BATCH * IDIM);

    const int jt = blockIdx.x;        // 0..31
    const int mt = blockIdx.y;        // 0..3
    const int p0 = jt * NT;

    const int tid = threadIdx.x;
    const int wid = tid >> 5, lid = tid & 31;
    const int kh = wid >> 2;          // 0..3 -> K quarter
    const int wm = wid & 1;           // 32-row half
    const int wn = (wid >> 1) & 1;    // 64-col half

    float acc[2][8][4] = {};

    // ---- h part: 32 kc from ping-pong h fragments ----
    {
        const float4* __restrict__ A0 =
            (const float4*)HXr + ((size_t)(mt * 4 + wm * 2) * NKCH + kh * 32) * 32 + lid;
        const float4* __restrict__ A1 = A0 + (size_t)NKCH * 32;
        const float4* __restrict__ B0 =
            (const float4*)g_Wf + ((size_t)(jt * 4 + wn * 2) * NKC + kh * 32) * 64 + lid;
        const float4* __restrict__ B1 = B0 + (size_t)NKC * 64;
#pragma unroll 8
        for (int i = 0; i < 32; ++i) {
            float4 a0 = __ldg(A0 + (size_t)i * 32);
            float4 a1 = __ldg(A1 + (size_t)i * 32);
            float4 b0 = __ldg(B0 + (size_t)i * 64);
            float4 b1 = __ldg(B0 + (size_t)i * 64 + 32);
            float4 b2 = __ldg(B1 + (size_t)i * 64);
            float4 b3 = __ldg(B1 + (size_t)i * 64 + 32);
            MMA_BODY();
        }
    }
    // ---- x part: 8 kc from pre-staged x fragments ----
    {
        const float4* __restrict__ A0 =
            (const float4*)Xf + ((size_t)(mt * 4 + wm * 2) * NKCX + kh * 8) * 32 + lid;
        const float4* __restrict__ A1 = A0 + (size_t)NKCX * 32;
        const float4* __restrict__ B0 =
            (const float4*)g_Wf + ((size_t)(jt * 4 + wn * 2) * NKC + NKCH + kh * 8) * 64 + lid;
        const float4* __restrict__ B1 = B0 + (size_t)NKC * 64;
#pragma unroll
        for (int i = 0; i < 8; ++i) {
            float4 a0 = __ldg(A0 + (size_t)i * 32);
            float4 a1 = __ldg(A1 + (size_t)i * 32);
            float4 b0 = __ldg(B0 + (size_t)i * 64);
            float4 b1 = __ldg(B0 + (size_t)i * 64 + 32);
            float4 b2 = __ldg(B1 + (size_t)i * 64);
            float4 b3 = __ldg(B1 + (size_t)i * 64 + 32);
            MMA_BODY();
        }
    }

    // single-pass: each kh quarter stores to its own region; one barrier
    {
        float* Gr = Gsm + kh * (MT * GLD);
        const int row = wm * 32 + (lid >> 2);
        const int col = wn * 64 + 2 * (lid & 3);
#pragma unroll
        for (int i = 0; i < 2; ++i)
#pragma unroll
            for (int nb = 0; nb < 8; ++nb) {
                *(float2*)(Gr + (row + i * 16) * GLD + col + nb * 8) =
                    make_float2(acc[i][nb][0], acc[i][nb][1]);
                *(float2*)(Gr + (row + i * 16 + 8) * GLD + col + nb * 8) =
                    make_float2(acc[i][nb][2], acc[i][nb][3]);
            }
    }
    __syncthreads();

    // fused LSTM cell epilogue, fragment-ordered I/O (coalesced float4).
    // Warp wid handles (local strip, local kc) = (wid&3, wid>>2); thread lid
    // owns one fragment slot = 4 consecutive floats (r = 0..3).
    {
        const float* Ga = Gsm;
        const float* Gb = Gsm + MT * GLD;
        const float* Gc = Gsm + 2 * MT * GLD;
        const float* Gd = Gsm + 3 * MT * GLD;

        const int strip_l = wid & 3;
        const int kc_l = wid >> 2;
        const int strip_g = mt * 4 + strip_l;
        const int kc_g = jt * 4 + kc_l;
        const size_t fbase = (((size_t)strip_g * NKCH + kc_g) * 32 + lid) * 4;

        float4 cold4 = *(const float4*)(g_Cf + fbase);
        float coldv[4] = {cold4.x, cold4.y, cold4.z, cold4.w};
        float cn[4], hn[4];
#pragma unroll
        for (int r = 0; r < 4; ++r) {
            int ml = strip_l * 16 + (lid >> 2) + 8 * (r & 1);
            int hh = kc_l * 8 + (lid & 3) + 4 * (r >> 1);
            int base = ml * GLD + hh;
            float il = (Ga[base]      + Gb[base])      + (Gc[base]      + Gd[base])      + g_BiasPack[p0 + hh];
            float fl = (Ga[base + 32] + Gb[base + 32]) + (Gc[base + 32] + Gd[base + 32]) + g_BiasPack[p0 + 32 + hh];
            float gl = (Ga[base + 64] + Gb[base + 64]) + (Gc[base + 64] + Gd[base + 64]) + g_BiasPack[p0 + 64 + hh];
            float ol = (Ga[base + 96] + Gb[base + 96]) + (Gc[base + 96] + Gd[base + 96]) + g_BiasPack[p0 + 96 + hh];
            float ig = fsigmoid(il);
            float fg = fsigmoid(fl);
            float gt = ftanh(gl);
            float og = fsigmoid(ol);
            float c = fg * coldv[r] + ig * gt;
            cn[r] = c;
            hn[r] = tf32r(og * ftanh(c));
        }
        *(float4*)(g_Cf + fbase) = make_float4(cn[0], cn[1], cn[2], cn[3]);
        *(float4*)(HXw + fbase)  = make_float4(hn[0], hn[1], hn[2], hn[3]);
    }
}

// out[m] = c[m,:] . fc_w + fc_b  (C is in h-fragment order)
__global__ void k_fc(const float* __restrict__ fc_w, const float* __restrict__ fc_b,
                     float* __restrict__ out) {
    int m = blockIdx.x;
    float s = 0.f;
    for (int k = threadIdx.x; k < HDIM; k += blockDim.x)
        s += g_Cf[hfrag_idx(m, k)] * fc_w[k];
#pragma unroll
    for (int o = 16; o; o >>= 1) s += __shfl_xor_sync(0xffffffffu, s, o);
    __shared__ float red[32];
    if ((threadIdx.x & 31) == 0) red[threadIdx.x >> 5] = s;
    __syncthreads();
    if (threadIdx.x < 32) {
        float v = (threadIdx.x < (int)(blockDim.x >> 5)) ? red[threadIdx.x] : 0.f;
#pragma unroll
        for (int o = 16; o; o >>= 1) v += __shfl_xor_sync(0xffffffffu, v, o);
        if (threadIdx.x == 0) out[m] = v + fc_b[0];
    }
}

extern "C" void kernel_launch(void* const* d_in, const int* in_sizes, int n_in,
                              void* d_out, int out_size) {
    (void)in_sizes; (void)n_in; (void)out_size;
    const float* ts   = (const float*)d_in[0];
    const float* w_ih = (const float*)d_in[1];
    const float* w_hh = (const float*)d_in[2];
    const float* b_ih = (const float*)d_in[3];
    const float* b_hh = (const float*)d_in[4];
    const float* fc_w = (const float*)d_in[5];
    const float* fc_b = (const float*)d_in[6];
    float* out = (float*)d_out;

    cudaFuncSetAttribute(k_step, cudaFuncAttributeMaxDynamicSharedMemorySize, SMEM_BYTES);

    k_convert<<<512, 256>>>(w_ih, w_hh, b_ih, b_hh);
    k_init<<<(BATCH * HDIM + 255) / 256, 256>>>();
    k_xstage<<<2048, 256>>>(ts);

    dim3 grid(32, 4);
    for (int t = 0; t < TSTEPS; ++t)
        k_step<<<grid, NTHR, SMEM_BYTES>>>(t);

    k_fc<<<BATCH, 256>>>(fc_w, fc_b, out);
}